// round 7
// baseline (speedup 1.0000x reference)
#include <cuda_runtime.h>
#include <cuda_bf16.h>
#include <cstdint>

#define NB 8192
#define NK 8192
#define ND 512
#define NM (8192ULL * 8192ULL)
#define GK 1536
#define SWB 256   // sweep blocks
#define SWR 32    // rows per sweep block

// ---------------- static device scratch ----------------
__device__ float  g_za[NM];
__device__ float  g_Dm[NM];
__device__ __nv_bfloat16 g_Xe[8192ULL * GK];  // [x1|x1|x2]
__device__ __nv_bfloat16 g_Ce[8192ULL * GK];  // [c1|c2|c1]
__device__ float2 g_colpart[(size_t)SWB * NK]; // per-block column partials (m, e)
__device__ float  g_nx[NB];
__device__ float  g_nc[NK];
__device__ double g_r[NB];
__device__ double g_c[NK];
__device__ float  g_zc[NK];
__device__ double g_Spart[16384];
__device__ double g_S;
__device__ unsigned g_maxbits;
__device__ unsigned g_minbits;
__device__ float  g_midf;
__device__ float  g_rangef;
__device__ int    g_idx[NB];

__device__ __forceinline__ unsigned encf(float f) {
    unsigned u = __float_as_uint(f);
    return (u & 0x80000000u) ? ~u : (u | 0x80000000u);
}
__device__ __forceinline__ float decf(unsigned u) {
    return (u & 0x80000000u) ? __uint_as_float(u & 0x7FFFFFFFu) : __uint_as_float(~u);
}
__device__ __forceinline__ float log2_of_double(double v) {
    int e; double m = frexp(v, &e);
    return (float)e + log2f((float)m);
}
__device__ __forceinline__ uint32_t smem_u32(const void* p) {
    uint32_t a;
    asm("{ .reg .u64 t; cvta.to.shared.u64 t, %1; cvt.u32.u64 %0, t; }" : "=r"(a) : "l"(p));
    return a;
}
__device__ __forceinline__ void cpa16(uint32_t s, const void* g) {
    asm volatile("cp.async.cg.shared.global [%0], [%1], 16;" :: "r"(s), "l"(g) : "memory");
}
#define CPA_COMMIT() asm volatile("cp.async.commit_group;" ::: "memory")
template <int N> __device__ __forceinline__ void cpa_wait() {
    asm volatile("cp.async.wait_group %0;" :: "n"(N) : "memory");
}
__device__ __forceinline__ void ldsm4(uint32_t* r, uint32_t addr) {
    asm volatile("ldmatrix.sync.aligned.m8n8.x4.shared.b16 {%0,%1,%2,%3}, [%4];"
        : "=r"(r[0]), "=r"(r[1]), "=r"(r[2]), "=r"(r[3]) : "r"(addr));
}
__device__ __forceinline__ void mma16816(float* d, const uint32_t* a, uint32_t b0, uint32_t b1) {
    asm volatile("mma.sync.aligned.m16n8k16.row.col.f32.bf16.bf16.f32 "
        "{%0,%1,%2,%3}, {%4,%5,%6,%7}, {%8,%9}, {%0,%1,%2,%3};"
        : "+f"(d[0]), "+f"(d[1]), "+f"(d[2]), "+f"(d[3])
        : "r"(a[0]), "r"(a[1]), "r"(a[2]), "r"(a[3]), "r"(b0), "r"(b1));
}

// ---------------- reset ----------------
__global__ void reset_kernel() {
    if (threadIdx.x == 0) { g_maxbits = 0u; g_minbits = 0xFFFFFFFFu; }
}

// ---------------- row norms ----------------
__global__ __launch_bounds__(128) void norms_kernel(const float* __restrict__ X,
                                                    const float* __restrict__ C) {
    int row = blockIdx.x;
    const float* p = (blockIdx.y == 0 ? X : C) + (size_t)row * ND;
    float4 v = ((const float4*)p)[threadIdx.x];
    double s = (double)v.x * v.x + (double)v.y * v.y + (double)v.z * v.z + (double)v.w * v.w;
    for (int o = 16; o; o >>= 1) s += __shfl_down_sync(0xffffffffu, s, o);
    __shared__ double sm[4];
    if ((threadIdx.x & 31) == 0) sm[threadIdx.x >> 5] = s;
    __syncthreads();
    if (threadIdx.x == 0) {
        double t = (sm[0] + sm[1]) + (sm[2] + sm[3]);
        if (blockIdx.y == 0) g_nx[row] = (float)t; else g_nc[row] = (float)t;
    }
}

// ---------------- split-bf16 prep ----------------
__global__ __launch_bounds__(256) void split_kernel(const float* __restrict__ X,
                                                    const float* __restrict__ C) {
    size_t idx = (size_t)blockIdx.x * 256 + threadIdx.x;
    size_t row = idx >> 9, k = idx & 511;
    {
        float x = X[idx];
        __nv_bfloat16 b1 = __float2bfloat16(x);
        __nv_bfloat16 b2 = __float2bfloat16(x - __bfloat162float(b1));
        __nv_bfloat16* d = g_Xe + row * GK + k;
        d[0] = b1; d[512] = b1; d[1024] = b2;
    }
    {
        float c = C[idx];
        __nv_bfloat16 b1 = __float2bfloat16(c);
        __nv_bfloat16 b2 = __float2bfloat16(c - __bfloat162float(b1));
        __nv_bfloat16* d = g_Ce + row * GK + k;
        d[0] = b1; d[512] = b2; d[1024] = b1;
    }
}

// ---------------- tensor-core GEMM (unchanged from R6) ----------------
#define SPITCH 40
#define SBUF   (128 * SPITCH)

__global__ __launch_bounds__(256) void mma_gemm_kernel() {
    __shared__ __nv_bfloat16 sA[2 * SBUF];
    __shared__ __nv_bfloat16 sB[2 * SBUF];
    const int tid = threadIdx.x;
    const int lane = tid & 31, wid = tid >> 5;
    const int wm = wid & 3, wn = wid >> 2;
    const int bi = blockIdx.y << 7, bj = blockIdx.x << 7;
    const uint32_t sAu = smem_u32(sA), sBu = smem_u32(sB);
    const __nv_bfloat16* Ag = g_Xe + (size_t)bi * GK;
    const __nv_bfloat16* Bg = g_Ce + (size_t)bj * GK;

    float acc[2][8][4];
#pragma unroll
    for (int t = 0; t < 2; t++)
#pragma unroll
        for (int u = 0; u < 8; u++)
#pragma unroll
            for (int v = 0; v < 4; v++) acc[t][u][v] = 0.f;

#define LOAD_CHUNK(c, buf)                                                          \
    {                                                                               \
        _Pragma("unroll")                                                           \
        for (int t = 0; t < 2; t++) {                                               \
            int s = tid + (t << 8);                                                 \
            int r = s >> 2, sg = (s & 3) << 3;                                      \
            uint32_t so = (buf) * (SBUF * 2) + r * (SPITCH * 2) + sg * 2;           \
            const size_t go = (size_t)r * GK + (c) * 32 + sg;                       \
            cpa16(sAu + so, Ag + go);                                               \
            cpa16(sBu + so, Bg + go);                                               \
        }                                                                           \
    }

    LOAD_CHUNK(0, 0);
    CPA_COMMIT();

    const uint32_t aRowOff = (uint32_t)(wm * 32 + (lane & 15)) * (SPITCH * 2);
    const uint32_t aColOff = (uint32_t)((lane >> 4) << 3) * 2;
    const uint32_t bRowBase = (uint32_t)(wn * 64 + (lane & 7) + (((lane >> 4) & 1) << 3));
    const uint32_t bColOff = (uint32_t)(((lane >> 3) & 1) << 3) * 2;

    for (int c = 0; c < GK / 32; c++) {
        int buf = c & 1;
        if (c + 1 < GK / 32) LOAD_CHUNK(c + 1, buf ^ 1);
        CPA_COMMIT();
        cpa_wait<1>();
        __syncthreads();
        uint32_t abase = sAu + buf * (SBUF * 2);
        uint32_t bbase = sBu + buf * (SBUF * 2);
#pragma unroll
        for (int kk = 0; kk < 2; kk++) {
            uint32_t a[2][4], b[4][4];
#pragma unroll
            for (int t = 0; t < 2; t++)
                ldsm4(a[t], abase + aRowOff + (uint32_t)(t * 16) * (SPITCH * 2)
                            + aColOff + (uint32_t)(kk * 16) * 2);
#pragma unroll
            for (int p = 0; p < 4; p++)
                ldsm4(b[p], bbase + (bRowBase + p * 16) * (SPITCH * 2)
                            + bColOff + (uint32_t)(kk * 16) * 2);
#pragma unroll
            for (int t = 0; t < 2; t++)
#pragma unroll
                for (int u = 0; u < 8; u++)
                    mma16816(acc[t][u], a[t], b[u >> 1][(u & 1) << 1], b[u >> 1][((u & 1) << 1) + 1]);
        }
        __syncthreads();
    }

    float lmx = -3.4e38f, lmn = 3.4e38f;
#pragma unroll
    for (int t = 0; t < 2; t++) {
        int r0 = bi + wm * 32 + t * 16 + (lane >> 2);
        float nx0 = g_nx[r0], nx1 = g_nx[r0 + 8];
#pragma unroll
        for (int u = 0; u < 8; u++) {
            int col = bj + wn * 64 + u * 8 + ((lane & 3) << 1);
            float nc0 = g_nc[col], nc1 = g_nc[col + 1];
            float d00 = (nx0 + nc0) - 2.0f * acc[t][u][0];
            float d01 = (nx0 + nc1) - 2.0f * acc[t][u][1];
            float d10 = (nx1 + nc0) - 2.0f * acc[t][u][2];
            float d11 = (nx1 + nc1) - 2.0f * acc[t][u][3];
            *(float2*)(g_Dm + (size_t)r0 * NK + col) = make_float2(d00, d01);
            *(float2*)(g_Dm + (size_t)(r0 + 8) * NK + col) = make_float2(d10, d11);
            lmx = fmaxf(lmx, fmaxf(fmaxf(d00, d01), fmaxf(d10, d11)));
            lmn = fminf(lmn, fminf(fminf(d00, d01), fminf(d10, d11)));
        }
    }
    for (int o = 16; o; o >>= 1) {
        lmx = fmaxf(lmx, __shfl_down_sync(0xffffffffu, lmx, o));
        lmn = fminf(lmn, __shfl_down_sync(0xffffffffu, lmn, o));
    }
    __shared__ float smx[8], smn[8];
    if (lane == 0) { smx[wid] = lmx; smn[wid] = lmn; }
    __syncthreads();
    if (tid == 0) {
#pragma unroll
        for (int w = 1; w < 8; w++) { lmx = fmaxf(lmx, smx[w]); lmn = fminf(lmn, smn[w]); }
        atomicMax(&g_maxbits, encf(lmx));
        atomicMin(&g_minbits, encf(lmn));
    }
}

__global__ void finalize_kernel() {
    float mx = decf(g_maxbits), mn = decf(g_minbits);
    float mid = (mx + mn) * 0.5f;
    g_midf = mid;
    g_rangef = (mx - mid) + 1e-8f;
}

// ---------------- fill: za + S partials (no transpose anymore) ----------------
__global__ __launch_bounds__(256) void fill_kernel() {
    __shared__ float sred[16];
    __shared__ float smb;
    const float midf = g_midf;
    const float rangef = g_rangef;
    const float cfh = -480.89834696298781f;
    const int tid = threadIdx.x;
    const int lane = tid & 31, warp = tid >> 5;
    const size_t i0 = (size_t)blockIdx.y * 64;
    const size_t j0 = (size_t)blockIdx.x * 64;
    const int r0 = tid >> 4;
    const int c4 = (tid & 15) << 2;

    float va[16];
    float mx = -3.4e38f;
#pragma unroll
    for (int k = 0; k < 4; k++) {
        int r = r0 + (k << 4);
        float4 d = *(const float4*)(g_Dm + (i0 + r) * NK + j0 + c4);
        float z0 = ((d.x - midf) / rangef) * cfh;
        float z1 = ((d.y - midf) / rangef) * cfh;
        float z2 = ((d.z - midf) / rangef) * cfh;
        float z3 = ((d.w - midf) / rangef) * cfh;
        va[k * 4 + 0] = z0; va[k * 4 + 1] = z1; va[k * 4 + 2] = z2; va[k * 4 + 3] = z3;
        *(float4*)(g_za + (i0 + r) * NK + j0 + c4) = make_float4(z0, z1, z2, z3);
        mx = fmaxf(mx, fmaxf(fmaxf(z0, z1), fmaxf(z2, z3)));
    }
    for (int o = 16; o; o >>= 1) mx = fmaxf(mx, __shfl_down_sync(0xffffffffu, mx, o));
    if (lane == 0) sred[warp] = mx;
    __syncthreads();
    if (tid == 0) {
        float m = sred[0];
#pragma unroll
        for (int w = 1; w < 8; w++) m = fmaxf(m, sred[w]);
        smb = floorf(m);
    }
    __syncthreads();
    const float mbf = smb;
    float s = 0.f;
#pragma unroll
    for (int k = 0; k < 16; k++) s += exp2f(va[k] - mbf);
    for (int o = 16; o; o >>= 1) s += __shfl_down_sync(0xffffffffu, s, o);
    if (lane == 0) sred[8 + warp] = s;
    __syncthreads();
    if (tid == 0) {
        float tot = 0.f;
#pragma unroll
        for (int w = 0; w < 8; w++) tot += sred[8 + w];
        g_Spart[blockIdx.y * 128 + blockIdx.x] = ldexp((double)tot, (int)mbf);
    }
}

__global__ __launch_bounds__(1024) void reduceS_kernel() {
    int tid = threadIdx.x;
    double s = 0.0;
#pragma unroll
    for (int k = 0; k < 16; k++) s += g_Spart[tid + k * 1024];
    __shared__ double sm[1024];
    sm[tid] = s;
    __syncthreads();
    for (int o = 512; o; o >>= 1) {
        if (tid < o) sm[tid] += sm[tid + o];
        __syncthreads();
    }
    if (tid == 0) g_S = sm[0];
}

__global__ void init_rc_kernel() {
    int t = blockIdx.x * blockDim.x + threadIdx.x;
    double S = g_S;
    if (t < NB) g_r[t] = 1.0 / S;
    if (t < NK) { g_c[t] = 1.0; g_zc[t] = 0.0f; }
}

// ---------------- fused Sinkhorn sweep: row normalize + column partials ----------------
// One pass over za: per row i, y_i = sum_j 2^(za+zc); r' update; then accumulate
// column partials z_j += 2^(za_ij + log2 r'_i) into per-thread (m,e) registers.
__global__ __launch_bounds__(256) void sweep_kernel() {
    extern __shared__ float rbuf[];   // 2 * 8192 floats (cp.async double buffer)
    __shared__ float sred[16];
    __shared__ float sbc[2];          // [0]=mf, [1]=zrow
    const int tid = threadIdx.x;
    const int lane = tid & 31, warp = tid >> 5;
    const int row0 = blockIdx.x * SWR;
    const float4* zc4 = (const float4*)g_zc;
    const uint32_t rb = smem_u32(rbuf);

    float vm[32], ve[32];
#pragma unroll
    for (int k = 0; k < 32; k++) { vm[k] = 0.f; ve[k] = -3.4e38f; }

    // prefetch row 0 into buffer 0
#pragma unroll
    for (int k = 0; k < 8; k++)
        cpa16(rb + (uint32_t)(tid + (k << 8)) * 16,
              g_za + (size_t)row0 * NK + (size_t)(tid + (k << 8)) * 4);
    CPA_COMMIT();

    for (int r = 0; r < SWR; r++) {
        const int buf = r & 1;
        cpa_wait<0>();
        __syncthreads();
        if (r + 1 < SWR) {
            uint32_t dst = rb + (uint32_t)(buf ^ 1) * 32768u;
#pragma unroll
            for (int k = 0; k < 8; k++)
                cpa16(dst + (uint32_t)(tid + (k << 8)) * 16,
                      g_za + (size_t)(row0 + r + 1) * NK + (size_t)(tid + (k << 8)) * 4);
            CPA_COMMIT();
        }
        const float4* a4 = (const float4*)(rbuf + buf * 8192);

        // pass 1: row max of za+zc
        float mx = -3.4e38f;
#pragma unroll
        for (int k = 0; k < 8; k++) {
            int j4 = tid + (k << 8);
            float4 a = a4[j4];
            float4 c = __ldg(&zc4[j4]);
            mx = fmaxf(mx, fmaxf(fmaxf(a.x + c.x, a.y + c.y), fmaxf(a.z + c.z, a.w + c.w)));
        }
        for (int o = 16; o; o >>= 1) mx = fmaxf(mx, __shfl_down_sync(0xffffffffu, mx, o));
        if (lane == 0) sred[warp] = mx;
        __syncthreads();
        if (tid == 0) {
            float m = sred[0];
#pragma unroll
            for (int w = 1; w < 8; w++) m = fmaxf(m, sred[w]);
            sbc[0] = floorf(m);
        }
        __syncthreads();
        const float mf = sbc[0];

        // pass 2: row sum, r update
        float s = 0.f;
#pragma unroll
        for (int k = 0; k < 8; k++) {
            int j4 = tid + (k << 8);
            float4 a = a4[j4];
            float4 c = __ldg(&zc4[j4]);
            s += exp2f(a.x + c.x - mf) + exp2f(a.y + c.y - mf)
               + exp2f(a.z + c.z - mf) + exp2f(a.w + c.w - mf);
        }
        for (int o = 16; o; o >>= 1) s += __shfl_down_sync(0xffffffffu, s, o);
        if (lane == 0) sred[8 + warp] = s;
        __syncthreads();
        if (tid == 0) {
            float tot = 0.f;
#pragma unroll
            for (int w = 0; w < 8; w++) tot += sred[8 + w];
            double y = ldexp((double)tot, (int)mf);
            double v = g_r[row0 + r];
            double vn = v / ((v * y) + 1e-8) / 8192.0;
            g_r[row0 + r] = vn;
            sbc[1] = log2_of_double(vn);
        }
        __syncthreads();
        const float zr = sbc[1];

        // pass 3: column accumulate with new r (thread-private, no barrier)
#pragma unroll
        for (int k = 0; k < 8; k++) {
            int j4 = tid + (k << 8);
            float4 a = a4[j4];
            float u[4] = { a.x + zr, a.y + zr, a.z + zr, a.w + zr };
#pragma unroll
            for (int i = 0; i < 4; i++) {
                int b = k * 4 + i;
                float e = ve[b], m = vm[b];
                if (u[i] > e) { vm[b] = m * exp2f(e - u[i]) + 1.0f; ve[b] = u[i]; }
                else          { vm[b] = m + exp2f(u[i] - e); }
            }
        }
    }

    // write column partials (coalesced: thread owns cols 4*j4 .. 4*j4+3)
    float2* cp = g_colpart + (size_t)blockIdx.x * NK;
#pragma unroll
    for (int k = 0; k < 8; k++) {
        int j4 = tid + (k << 8);
#pragma unroll
        for (int i = 0; i < 4; i++)
            cp[j4 * 4 + i] = make_float2(vm[k * 4 + i], ve[k * 4 + i]);
    }
}

// ---------------- column update: combine partials, update c/zc ----------------
__global__ __launch_bounds__(256) void colupd_kernel() {
    int j = blockIdx.x * 256 + threadIdx.x;
    float M = 0.f, E = -3.4e38f;
    for (int b = 0; b < SWB; b++) {
        float2 p = g_colpart[(size_t)b * NK + j];
        if (p.y > E) { M = M * exp2f(E - p.y) + p.x; E = p.y; }
        else         { M += p.x * exp2f(p.y - E); }
    }
    double z;
    if (E < -1200.0f) z = 0.0;
    else {
        int Ei = (int)floorf(E);
        z = ldexp((double)(M * exp2f(E - (float)Ei)), Ei);
    }
    double c = g_c[j];
    double cn = c / ((c * z) + 1e-8) / 8192.0;
    g_c[j] = cn;
    g_zc[j] = log2_of_double(cn);
}

// ---------------- probs + argmax ----------------
__global__ __launch_bounds__(256) void probs_kernel(float* __restrict__ out_probs,
                                                    float* __restrict__ out_idx) {
    __shared__ float szc[NK];
    __shared__ float sred[8];
    __shared__ int sidx[8];
    const int tid = threadIdx.x;
    const int lane = tid & 31, warp = tid >> 5;
    for (int k = tid; k < NK / 4; k += 256)
        ((float4*)szc)[k] = ((const float4*)g_zc)[k];
    __syncthreads();
#pragma unroll 1
    for (int rr = 0; rr < 4; rr++) {
        const int i = (blockIdx.x << 2) + rr;
        const float lR = log2_of_double(8192.0 * g_r[i]);
        const float4* a4 = (const float4*)(g_za + (size_t)i * NK);
        float4* o4 = (float4*)(out_probs + (size_t)i * NK);
        float best = -3.4e38f; int bj = 0x7FFFFFFF;
#pragma unroll
        for (int k = 0; k < 8; k++) {
            int j4 = tid + (k << 8);
            float4 a = a4[j4];
            float4 c = ((const float4*)szc)[j4];
            float t0 = a.x + c.x, t1 = a.y + c.y, t2 = a.z + c.z, t3 = a.w + c.w;
            o4[j4] = make_float4(exp2f(t0 + lR), exp2f(t1 + lR), exp2f(t2 + lR), exp2f(t3 + lR));
            int jb = j4 << 2;
            if (t0 > best) { best = t0; bj = jb; }
            if (t1 > best) { best = t1; bj = jb + 1; }
            if (t2 > best) { best = t2; bj = jb + 2; }
            if (t3 > best) { best = t3; bj = jb + 3; }
        }
        for (int o = 16; o; o >>= 1) {
            float ov = __shfl_down_sync(0xffffffffu, best, o);
            int oi = __shfl_down_sync(0xffffffffu, bj, o);
            if (ov > best || (ov == best && oi < bj)) { best = ov; bj = oi; }
        }
        if (lane == 0) { sred[warp] = best; sidx[warp] = bj; }
        __syncthreads();
        if (tid == 0) {
#pragma unroll
            for (int w = 1; w < 8; w++)
                if (sred[w] > best || (sred[w] == best && sidx[w] < bj)) { best = sred[w]; bj = sidx[w]; }
            g_idx[i] = bj;
            out_idx[i] = (float)bj;
        }
        __syncthreads();
    }
}

// ---------------- epilogue ----------------
__global__ __launch_bounds__(128) void epilogue_kernel(const float* __restrict__ X,
                                                       const float* __restrict__ C,
                                                       float* __restrict__ qh,
                                                       float* __restrict__ qs,
                                                       float* __restrict__ loss) {
    int i = blockIdx.x;
    int idx = g_idx[i];
    const float4* cb = (const float4*)(C + (size_t)idx * ND);
    const float4* xr = (const float4*)(X + (size_t)i * ND);
    float4* oh = (float4*)(qh + (size_t)i * ND);
    float4* os = (float4*)(qs + (size_t)i * ND);
    int t = threadIdx.x;
    float4 c4 = cb[t];
    float4 x4 = xr[t];
    oh[t] = c4;
    float dx = c4.x - x4.x, dy = c4.y - x4.y, dz = c4.z - x4.z, dw = c4.w - x4.w;
    os[t] = make_float4(dx + x4.x, dy + x4.y, dz + x4.z, dw + x4.w);
    double s = (double)dx * dx + (double)dy * dy + (double)dz * dz + (double)dw * dw;
    for (int o = 16; o; o >>= 1) s += __shfl_down_sync(0xffffffffu, s, o);
    __shared__ double sm[4];
    if ((t & 31) == 0) sm[t >> 5] = s;
    __syncthreads();
    if (t == 0) {
        double tot = (sm[0] + sm[1]) + (sm[2] + sm[3]);
        float cl = (float)(tot / (double)ND);
        loss[i] = cl + 0.25f * cl;
    }
}

// ---------------- launch ----------------
extern "C" void kernel_launch(void* const* d_in, const int* in_sizes, int n_in,
                              void* d_out, int out_size) {
    const float* X = (const float*)d_in[0];
    const float* C = (const float*)d_in[1];
    float* out = (float*)d_out;
    float* o_qh    = out;
    float* o_qs    = out + (size_t)NB * ND;
    float* o_idx   = out + 2ULL * NB * ND;
    float* o_probs = o_idx + NB;
    float* o_loss  = o_probs + NM;

    cudaFuncSetAttribute(sweep_kernel, cudaFuncAttributeMaxDynamicSharedMemorySize, 65536);

    reset_kernel<<<1, 32>>>();
    norms_kernel<<<dim3(NB, 2), 128>>>(X, C);
    split_kernel<<<16384, 256>>>(X, C);
    mma_gemm_kernel<<<dim3(64, 64), 256>>>();
    finalize_kernel<<<1, 1>>>();
    fill_kernel<<<dim3(128, 128), 256>>>();
    reduceS_kernel<<<1, 1024>>>();
    init_rc_kernel<<<32, 256>>>();
    for (int it = 0; it < 50; it++) {
        sweep_kernel<<<SWB, 256, 65536>>>();
        colupd_kernel<<<32, 256>>>();
    }
    probs_kernel<<<2048, 256>>>(o_probs, o_idx);
    epilogue_kernel<<<NB, 128>>>(X, C, o_qh, o_qs, o_loss);
}

// round 8
// speedup vs baseline: 2.2822x; 2.2822x over previous
#include <cuda_runtime.h>
#include <cuda_bf16.h>
#include <cstdint>

#define NB 8192
#define NK 8192
#define ND 512
#define NM (8192ULL * 8192ULL)
#define GK 1536

// ---------------- static device scratch ----------------
__device__ float  g_za[NM];
__device__ float  g_zaT[NM];
__device__ float  g_Dm[NM];
__device__ __nv_bfloat16 g_Xe[8192ULL * GK];  // [x1|x1|x2]
__device__ __nv_bfloat16 g_Ce[8192ULL * GK];  // [c1|c2|c1]
__device__ float  g_nx[NB];
__device__ float  g_nc[NK];
__device__ double g_r[NB];
__device__ double g_c[NK];
__device__ float  g_zr[NB];
__device__ float  g_zc[NK];
__device__ double g_Spart[16384];
__device__ double g_S;
__device__ unsigned g_maxbits;
__device__ unsigned g_minbits;
__device__ float  g_midf;
__device__ float  g_rangef;
__device__ int    g_idx[NB];

__device__ __forceinline__ unsigned encf(float f) {
    unsigned u = __float_as_uint(f);
    return (u & 0x80000000u) ? ~u : (u | 0x80000000u);
}
__device__ __forceinline__ float decf(unsigned u) {
    return (u & 0x80000000u) ? __uint_as_float(u & 0x7FFFFFFFu) : __uint_as_float(~u);
}
__device__ __forceinline__ float log2_of_double(double v) {
    int e; double m = frexp(v, &e);
    return (float)e + log2f((float)m);
}
__device__ __forceinline__ uint32_t smem_u32(const void* p) {
    uint32_t a;
    asm("{ .reg .u64 t; cvta.to.shared.u64 t, %1; cvt.u32.u64 %0, t; }" : "=r"(a) : "l"(p));
    return a;
}
__device__ __forceinline__ void cpa16(uint32_t s, const void* g) {
    asm volatile("cp.async.cg.shared.global [%0], [%1], 16;" :: "r"(s), "l"(g) : "memory");
}
#define CPA_COMMIT() asm volatile("cp.async.commit_group;" ::: "memory")
template <int N> __device__ __forceinline__ void cpa_wait() {
    asm volatile("cp.async.wait_group %0;" :: "n"(N) : "memory");
}
__device__ __forceinline__ void ldsm4(uint32_t* r, uint32_t addr) {
    asm volatile("ldmatrix.sync.aligned.m8n8.x4.shared.b16 {%0,%1,%2,%3}, [%4];"
        : "=r"(r[0]), "=r"(r[1]), "=r"(r[2]), "=r"(r[3]) : "r"(addr));
}
__device__ __forceinline__ void mma16816(float* d, const uint32_t* a, uint32_t b0, uint32_t b1) {
    asm volatile("mma.sync.aligned.m16n8k16.row.col.f32.bf16.bf16.f32 "
        "{%0,%1,%2,%3}, {%4,%5,%6,%7}, {%8,%9}, {%0,%1,%2,%3};"
        : "+f"(d[0]), "+f"(d[1]), "+f"(d[2]), "+f"(d[3])
        : "r"(a[0]), "r"(a[1]), "r"(a[2]), "r"(a[3]), "r"(b0), "r"(b1));
}

// ---------------- reset ----------------
__global__ void reset_kernel() {
    if (threadIdx.x == 0) { g_maxbits = 0u; g_minbits = 0xFFFFFFFFu; }
}

// ---------------- row norms ----------------
__global__ __launch_bounds__(128) void norms_kernel(const float* __restrict__ X,
                                                    const float* __restrict__ C) {
    int row = blockIdx.x;
    const float* p = (blockIdx.y == 0 ? X : C) + (size_t)row * ND;
    float4 v = ((const float4*)p)[threadIdx.x];
    double s = (double)v.x * v.x + (double)v.y * v.y + (double)v.z * v.z + (double)v.w * v.w;
    for (int o = 16; o; o >>= 1) s += __shfl_down_sync(0xffffffffu, s, o);
    __shared__ double sm[4];
    if ((threadIdx.x & 31) == 0) sm[threadIdx.x >> 5] = s;
    __syncthreads();
    if (threadIdx.x == 0) {
        double t = (sm[0] + sm[1]) + (sm[2] + sm[3]);
        if (blockIdx.y == 0) g_nx[row] = (float)t; else g_nc[row] = (float)t;
    }
}

// ---------------- split-bf16 prep ----------------
__global__ __launch_bounds__(256) void split_kernel(const float* __restrict__ X,
                                                    const float* __restrict__ C) {
    size_t idx = (size_t)blockIdx.x * 256 + threadIdx.x;
    size_t row = idx >> 9, k = idx & 511;
    {
        float x = X[idx];
        __nv_bfloat16 b1 = __float2bfloat16(x);
        __nv_bfloat16 b2 = __float2bfloat16(x - __bfloat162float(b1));
        __nv_bfloat16* d = g_Xe + row * GK + k;
        d[0] = b1; d[512] = b1; d[1024] = b2;
    }
    {
        float c = C[idx];
        __nv_bfloat16 b1 = __float2bfloat16(c);
        __nv_bfloat16 b2 = __float2bfloat16(c - __bfloat162float(b1));
        __nv_bfloat16* d = g_Ce + row * GK + k;
        d[0] = b1; d[512] = b2; d[1024] = b1;
    }
}

// ---------------- tensor-core GEMM (R6, unchanged) ----------------
#define SPITCH 40
#define SBUF   (128 * SPITCH)

__global__ __launch_bounds__(256) void mma_gemm_kernel() {
    __shared__ __nv_bfloat16 sA[2 * SBUF];
    __shared__ __nv_bfloat16 sB[2 * SBUF];
    const int tid = threadIdx.x;
    const int lane = tid & 31, wid = tid >> 5;
    const int wm = wid & 3, wn = wid >> 2;
    const int bi = blockIdx.y << 7, bj = blockIdx.x << 7;
    const uint32_t sAu = smem_u32(sA), sBu = smem_u32(sB);
    const __nv_bfloat16* Ag = g_Xe + (size_t)bi * GK;
    const __nv_bfloat16* Bg = g_Ce + (size_t)bj * GK;

    float acc[2][8][4];
#pragma unroll
    for (int t = 0; t < 2; t++)
#pragma unroll
        for (int u = 0; u < 8; u++)
#pragma unroll
            for (int v = 0; v < 4; v++) acc[t][u][v] = 0.f;

#define LOAD_CHUNK(c, buf)                                                          \
    {                                                                               \
        _Pragma("unroll")                                                           \
        for (int t = 0; t < 2; t++) {                                               \
            int s = tid + (t << 8);                                                 \
            int r = s >> 2, sg = (s & 3) << 3;                                      \
            uint32_t so = (buf) * (SBUF * 2) + r * (SPITCH * 2) + sg * 2;           \
            const size_t go = (size_t)r * GK + (c) * 32 + sg;                       \
            cpa16(sAu + so, Ag + go);                                               \
            cpa16(sBu + so, Bg + go);                                               \
        }                                                                           \
    }

    LOAD_CHUNK(0, 0);
    CPA_COMMIT();

    const uint32_t aRowOff = (uint32_t)(wm * 32 + (lane & 15)) * (SPITCH * 2);
    const uint32_t aColOff = (uint32_t)((lane >> 4) << 3) * 2;
    const uint32_t bRowBase = (uint32_t)(wn * 64 + (lane & 7) + (((lane >> 4) & 1) << 3));
    const uint32_t bColOff = (uint32_t)(((lane >> 3) & 1) << 3) * 2;

    for (int c = 0; c < GK / 32; c++) {
        int buf = c & 1;
        if (c + 1 < GK / 32) LOAD_CHUNK(c + 1, buf ^ 1);
        CPA_COMMIT();
        cpa_wait<1>();
        __syncthreads();
        uint32_t abase = sAu + buf * (SBUF * 2);
        uint32_t bbase = sBu + buf * (SBUF * 2);
#pragma unroll
        for (int kk = 0; kk < 2; kk++) {
            uint32_t a[2][4], b[4][4];
#pragma unroll
            for (int t = 0; t < 2; t++)
                ldsm4(a[t], abase + aRowOff + (uint32_t)(t * 16) * (SPITCH * 2)
                            + aColOff + (uint32_t)(kk * 16) * 2);
#pragma unroll
            for (int p = 0; p < 4; p++)
                ldsm4(b[p], bbase + (bRowBase + p * 16) * (SPITCH * 2)
                            + bColOff + (uint32_t)(kk * 16) * 2);
#pragma unroll
            for (int t = 0; t < 2; t++)
#pragma unroll
                for (int u = 0; u < 8; u++)
                    mma16816(acc[t][u], a[t], b[u >> 1][(u & 1) << 1], b[u >> 1][((u & 1) << 1) + 1]);
        }
        __syncthreads();
    }

    float lmx = -3.4e38f, lmn = 3.4e38f;
#pragma unroll
    for (int t = 0; t < 2; t++) {
        int r0 = bi + wm * 32 + t * 16 + (lane >> 2);
        float nx0 = g_nx[r0], nx1 = g_nx[r0 + 8];
#pragma unroll
        for (int u = 0; u < 8; u++) {
            int col = bj + wn * 64 + u * 8 + ((lane & 3) << 1);
            float nc0 = g_nc[col], nc1 = g_nc[col + 1];
            float d00 = (nx0 + nc0) - 2.0f * acc[t][u][0];
            float d01 = (nx0 + nc1) - 2.0f * acc[t][u][1];
            float d10 = (nx1 + nc0) - 2.0f * acc[t][u][2];
            float d11 = (nx1 + nc1) - 2.0f * acc[t][u][3];
            *(float2*)(g_Dm + (size_t)r0 * NK + col) = make_float2(d00, d01);
            *(float2*)(g_Dm + (size_t)(r0 + 8) * NK + col) = make_float2(d10, d11);
            lmx = fmaxf(lmx, fmaxf(fmaxf(d00, d01), fmaxf(d10, d11)));
            lmn = fminf(lmn, fminf(fminf(d00, d01), fminf(d10, d11)));
        }
    }
    for (int o = 16; o; o >>= 1) {
        lmx = fmaxf(lmx, __shfl_down_sync(0xffffffffu, lmx, o));
        lmn = fminf(lmn, __shfl_down_sync(0xffffffffu, lmn, o));
    }
    __shared__ float smx[8], smn[8];
    if (lane == 0) { smx[wid] = lmx; smn[wid] = lmn; }
    __syncthreads();
    if (tid == 0) {
#pragma unroll
        for (int w = 1; w < 8; w++) { lmx = fmaxf(lmx, smx[w]); lmn = fminf(lmn, smn[w]); }
        atomicMax(&g_maxbits, encf(lmx));
        atomicMin(&g_minbits, encf(lmn));
    }
}

__global__ void finalize_kernel() {
    float mx = decf(g_maxbits), mn = decf(g_minbits);
    float mid = (mx + mn) * 0.5f;
    g_midf = mid;
    g_rangef = (mx - mid) + 1e-8f;
}

// ---------------- fill: za + zaT + S partials (R6) ----------------
__global__ __launch_bounds__(256) void fill_kernel() {
    __shared__ float tile[64][65];
    __shared__ float sred[16];
    __shared__ float smb;
    const float midf = g_midf;
    const float rangef = g_rangef;
    const float cfh = -480.89834696298781f;
    const int tid = threadIdx.x;
    const int lane = tid & 31, warp = tid >> 5;
    const size_t i0 = (size_t)blockIdx.y * 64;
    const size_t j0 = (size_t)blockIdx.x * 64;
    const int r0 = tid >> 4;
    const int c4 = (tid & 15) << 2;

    float va[16];
    float mx = -3.4e38f;
#pragma unroll
    for (int k = 0; k < 4; k++) {
        int r = r0 + (k << 4);
        float4 d = *(const float4*)(g_Dm + (i0 + r) * NK + j0 + c4);
        float z0 = ((d.x - midf) / rangef) * cfh;
        float z1 = ((d.y - midf) / rangef) * cfh;
        float z2 = ((d.z - midf) / rangef) * cfh;
        float z3 = ((d.w - midf) / rangef) * cfh;
        va[k * 4 + 0] = z0; va[k * 4 + 1] = z1; va[k * 4 + 2] = z2; va[k * 4 + 3] = z3;
        tile[r][c4 + 0] = z0; tile[r][c4 + 1] = z1; tile[r][c4 + 2] = z2; tile[r][c4 + 3] = z3;
        *(float4*)(g_za + (i0 + r) * NK + j0 + c4) = make_float4(z0, z1, z2, z3);
        mx = fmaxf(mx, fmaxf(fmaxf(z0, z1), fmaxf(z2, z3)));
    }
    for (int o = 16; o; o >>= 1) mx = fmaxf(mx, __shfl_down_sync(0xffffffffu, mx, o));
    if (lane == 0) sred[warp] = mx;
    __syncthreads();
    if (tid == 0) {
        float m = sred[0];
#pragma unroll
        for (int w = 1; w < 8; w++) m = fmaxf(m, sred[w]);
        smb = floorf(m);
    }
    __syncthreads();
    const float mbf = smb;
    float s = 0.f;
#pragma unroll
    for (int k = 0; k < 16; k++) s += exp2f(va[k] - mbf);
    for (int o = 16; o; o >>= 1) s += __shfl_down_sync(0xffffffffu, s, o);
    if (lane == 0) sred[8 + warp] = s;
    __syncthreads();
    if (tid == 0) {
        float tot = 0.f;
#pragma unroll
        for (int w = 0; w < 8; w++) tot += sred[8 + w];
        g_Spart[blockIdx.y * 128 + blockIdx.x] = ldexp((double)tot, (int)mbf);
    }
#pragma unroll
    for (int k = 0; k < 4; k++) {
        int r = r0 + (k << 4);
        float4 v = make_float4(tile[c4 + 0][r], tile[c4 + 1][r], tile[c4 + 2][r], tile[c4 + 3][r]);
        *(float4*)(g_zaT + (j0 + r) * NK + i0 + c4) = v;
    }
}

__global__ __launch_bounds__(1024) void reduceS_kernel() {
    int tid = threadIdx.x;
    double s = 0.0;
#pragma unroll
    for (int k = 0; k < 16; k++) s += g_Spart[tid + k * 1024];
    __shared__ double sm[1024];
    sm[tid] = s;
    __syncthreads();
    for (int o = 512; o; o >>= 1) {
        if (tid < o) sm[tid] += sm[tid + o];
        __syncthreads();
    }
    if (tid == 0) g_S = sm[0];
}

__global__ void init_rc_kernel() {
    int t = blockIdx.x * blockDim.x + threadIdx.x;
    double S = g_S;
    if (t < NB) { g_r[t] = 1.0 / S; g_zr[t] = -log2_of_double(S); }
    if (t < NK) { g_c[t] = 1.0;     g_zc[t] = 0.0f; }
}

// ---------------- Sinkhorn pass: warp-per-row, single read, barrier-free ----------------
__global__ __launch_bounds__(256) void pass_kernel(int dir) {
    const float* __restrict__ ZA   = dir ? g_zaT : g_za;
    const float* __restrict__ zo   = dir ? g_zr  : g_zc;
    double* __restrict__      vec  = dir ? g_c   : g_r;
    float* __restrict__       zvec = dir ? g_zc  : g_zr;

    const int lane = threadIdx.x & 31;
    const int i = (blockIdx.x << 3) + (threadIdx.x >> 5);
    const float4* a4 = (const float4*)(ZA + (size_t)i * NK);
    const float4* c4 = (const float4*)zo;

    float M = 0.f, E = -3.4e38f;
#pragma unroll 1
    for (int ch = 0; ch < 8; ch++) {
        float t[32];
        float cmx = -3.4e38f;
#pragma unroll
        for (int v = 0; v < 8; v++) {
            int j4 = (ch << 8) + (v << 5) + lane;
            float4 a = a4[j4];
            float4 c = __ldg(&c4[j4]);
            float t0 = a.x + c.x, t1 = a.y + c.y, t2 = a.z + c.z, t3 = a.w + c.w;
            t[v * 4 + 0] = t0; t[v * 4 + 1] = t1; t[v * 4 + 2] = t2; t[v * 4 + 3] = t3;
            cmx = fmaxf(cmx, fmaxf(fmaxf(t0, t1), fmaxf(t2, t3)));
        }
        float s0 = 0.f, s1 = 0.f, s2 = 0.f, s3 = 0.f;
#pragma unroll
        for (int v = 0; v < 8; v++) {
            s0 += exp2f(t[v * 4 + 0] - cmx);
            s1 += exp2f(t[v * 4 + 1] - cmx);
            s2 += exp2f(t[v * 4 + 2] - cmx);
            s3 += exp2f(t[v * 4 + 3] - cmx);
        }
        float s = (s0 + s1) + (s2 + s3);
        if (cmx > E) { M = M * exp2f(E - cmx) + s; E = cmx; }
        else         { M += s * exp2f(cmx - E); }
    }
    // warp (m,e) merge
    for (int o = 16; o; o >>= 1) {
        float oe = __shfl_down_sync(0xffffffffu, E, o);
        float om = __shfl_down_sync(0xffffffffu, M, o);
        if (oe > E) { M = M * exp2f(E - oe) + om; E = oe; }
        else        { M += om * exp2f(oe - E); }
    }
    if (lane == 0) {
        float Ei = floorf(E);
        double y = ldexp((double)(M * exp2f(E - Ei)), (int)Ei);
        double v = vec[i];
        double vn = v / ((v * y) + 1e-8) / 8192.0;
        vec[i] = vn;
        zvec[i] = log2_of_double(vn);
    }
}

// ---------------- probs + argmax: warp-per-row ----------------
__global__ __launch_bounds__(256) void probs_kernel(float* __restrict__ out_probs,
                                                    float* __restrict__ out_idx) {
    const int lane = threadIdx.x & 31;
    const int i = (blockIdx.x << 3) + (threadIdx.x >> 5);
    const float lR = log2_of_double(8192.0 * g_r[i]);
    const float4* a4 = (const float4*)(g_za + (size_t)i * NK);
    const float4* c4 = (const float4*)g_zc;
    float4* o4 = (float4*)(out_probs + (size_t)i * NK);

    float best = -3.4e38f; int bj = 0x7FFFFFFF;
#pragma unroll 4
    for (int v = 0; v < 64; v++) {
        int j4 = (v << 5) + lane;
        float4 a = a4[j4];
        float4 c = __ldg(&c4[j4]);
        float t0 = a.x + c.x, t1 = a.y + c.y, t2 = a.z + c.z, t3 = a.w + c.w;
        o4[j4] = make_float4(exp2f(t0 + lR), exp2f(t1 + lR), exp2f(t2 + lR), exp2f(t3 + lR));
        int jb = j4 << 2;
        if (t0 > best) { best = t0; bj = jb; }
        if (t1 > best) { best = t1; bj = jb + 1; }
        if (t2 > best) { best = t2; bj = jb + 2; }
        if (t3 > best) { best = t3; bj = jb + 3; }
    }
    for (int o = 16; o; o >>= 1) {
        float ov = __shfl_down_sync(0xffffffffu, best, o);
        int oi = __shfl_down_sync(0xffffffffu, bj, o);
        if (ov > best || (ov == best && oi < bj)) { best = ov; bj = oi; }
    }
    if (lane == 0) { g_idx[i] = bj; out_idx[i] = (float)bj; }
}

// ---------------- epilogue ----------------
__global__ __launch_bounds__(128) void epilogue_kernel(const float* __restrict__ X,
                                                       const float* __restrict__ C,
                                                       float* __restrict__ qh,
                                                       float* __restrict__ qs,
                                                       float* __restrict__ loss) {
    int i = blockIdx.x;
    int idx = g_idx[i];
    const float4* cb = (const float4*)(C + (size_t)idx * ND);
    const float4* xr = (const float4*)(X + (size_t)i * ND);
    float4* oh = (float4*)(qh + (size_t)i * ND);
    float4* os = (float4*)(qs + (size_t)i * ND);
    int t = threadIdx.x;
    float4 c4 = cb[t];
    float4 x4 = xr[t];
    oh[t] = c4;
    float dx = c4.x - x4.x, dy = c4.y - x4.y, dz = c4.z - x4.z, dw = c4.w - x4.w;
    os[t] = make_float4(dx + x4.x, dy + x4.y, dz + x4.z, dw + x4.w);
    double s = (double)dx * dx + (double)dy * dy + (double)dz * dz + (double)dw * dw;
    for (int o = 16; o; o >>= 1) s += __shfl_down_sync(0xffffffffu, s, o);
    __shared__ double sm[4];
    if ((t & 31) == 0) sm[t >> 5] = s;
    __syncthreads();
    if (t == 0) {
        double tot = (sm[0] + sm[1]) + (sm[2] + sm[3]);
        float cl = (float)(tot / (double)ND);
        loss[i] = cl + 0.25f * cl;
    }
}

// ---------------- launch ----------------
extern "C" void kernel_launch(void* const* d_in, const int* in_sizes, int n_in,
                              void* d_out, int out_size) {
    const float* X = (const float*)d_in[0];
    const float* C = (const float*)d_in[1];
    float* out = (float*)d_out;
    float* o_qh    = out;
    float* o_qs    = out + (size_t)NB * ND;
    float* o_idx   = out + 2ULL * NB * ND;
    float* o_probs = o_idx + NB;
    float* o_loss  = o_probs + NM;

    reset_kernel<<<1, 32>>>();
    norms_kernel<<<dim3(NB, 2), 128>>>(X, C);
    split_kernel<<<16384, 256>>>(X, C);
    mma_gemm_kernel<<<dim3(64, 64), 256>>>();
    finalize_kernel<<<1, 1>>>();
    fill_kernel<<<dim3(128, 128), 256>>>();
    reduceS_kernel<<<1, 1024>>>();
    init_rc_kernel<<<32, 256>>>();
    for (int it = 0; it < 50; it++) {
        pass_kernel<<<1024, 256>>>(0);
        pass_kernel<<<1024, 256>>>(1);
    }
    probs_kernel<<<1024, 256>>>(o_probs, o_idx);
    epilogue_kernel<<<NB, 128>>>(X, C, o_qh, o_qs, o_loss);
}